// round 3
// baseline (speedup 1.0000x reference)
#include <cuda_runtime.h>
#include <cuda_bf16.h>
#include <math.h>
#include <stdint.h>

// ---------------------------------------------------------------------------
// Shapes: B=64, C=2, N=1024, T=13, D=256. Output [64,1024,1024] fp32.
// ---------------------------------------------------------------------------

#define BB   64
#define NN   1024
#define DD   256
#define CT   26      // C*T contraction length

// Scratch (device globals; allocation-free per harness rules)
__device__ __align__(16) __nv_bfloat16 g_c[BB * NN * DD];        // 32 MB  (rank-127.5 as bf16)
__device__ __align__(16) float g_adj[(size_t)BB * NN * NN];      // 268 MB
__device__ float g_psum[BB * 8 * NN];                            // per n-tile partial row sums
__device__ float g_psq [BB * 8 * NN];
__device__ float g_mean[BB * NN];
__device__ float g_rstd[BB * NN];

// ---------------------------------------------------------------------------
// K1: conv (einsum bcnt,dct->bnd) + bias + LayerNorm(D) + stable rank via
//     bitonic sort of (sortable_bits<<32 | idx). One block = 8 rows, 256 thr.
// ---------------------------------------------------------------------------
__global__ void k1_emb_rank(const float* __restrict__ x,
                            const float* __restrict__ conv_w,
                            const float* __restrict__ conv_b,
                            const float* __restrict__ time_g,
                            const float* __restrict__ time_b) {
    __shared__ float ws[DD * CT];          // 26.6 KB
    __shared__ float xs[8][CT];
    __shared__ unsigned long long keys[DD];
    __shared__ float red[16];

    const int tid = threadIdx.x;           // 0..255 == d
    const int b   = blockIdx.y;
    const int n0  = blockIdx.x * 8;

    for (int i = tid; i < DD * CT; i += 256) ws[i] = conv_w[i];
    if (tid < 8 * CT) {
        int r = tid / CT, j = tid % CT;
        int c = j / 13, t = j % 13;
        xs[r][j] = x[(((size_t)(b * 2 + c) * NN) + (n0 + r)) * 13 + t];
    }
    __syncthreads();

    const float tg = time_g[tid];
    const float tb = time_b[tid];
    const float cb = conv_b[tid];

    for (int r = 0; r < 8; ++r) {
        float acc = cb;
        #pragma unroll
        for (int j = 0; j < CT; ++j) acc += xs[r][j] * ws[tid * CT + j];

        // block LayerNorm over 256
        float s = acc, q = acc * acc;
        #pragma unroll
        for (int o = 16; o; o >>= 1) {
            s += __shfl_xor_sync(0xffffffffu, s, o);
            q += __shfl_xor_sync(0xffffffffu, q, o);
        }
        if ((tid & 31) == 0) { red[tid >> 5] = s; red[8 + (tid >> 5)] = q; }
        __syncthreads();
        if (tid == 0) {
            float S = 0.f, Q = 0.f;
            #pragma unroll
            for (int i = 0; i < 8; ++i) { S += red[i]; Q += red[8 + i]; }
            float mu  = S * (1.0f / 256.0f);
            float var = Q * (1.0f / 256.0f) - mu * mu;
            red[0] = mu;
            red[1] = rsqrtf(var + 1e-5f);
        }
        __syncthreads();
        float v = (acc - red[0]) * red[1] * tg + tb;

        // sortable key (ascending float order), stable tie-break by index
        unsigned kb = __float_as_uint(v);
        kb = (kb & 0x80000000u) ? ~kb : (kb | 0x80000000u);
        keys[tid] = ((unsigned long long)kb << 32) | (unsigned)tid;
        __syncthreads();

        // bitonic sort, 256 elements
        for (int k = 2; k <= 256; k <<= 1) {
            for (int j = k >> 1; j > 0; j >>= 1) {
                int p = tid ^ j;
                if (p > tid) {
                    bool up = ((tid & k) == 0);
                    unsigned long long a = keys[tid], bkey = keys[p];
                    if ((a > bkey) == up) { keys[tid] = bkey; keys[p] = a; }
                }
                __syncthreads();
            }
        }
        // position tid holds original index -> rank[idx] = tid
        int idx = (int)(keys[tid] & 0xFFu);
        g_c[((size_t)(b * NN + n0 + r) << 8) + idx] =
            __float2bfloat16((float)tid - 127.5f);
        __syncthreads();
    }
}

// ---------------------------------------------------------------------------
// K2: per-batch GEMM S = C * C^T via mma.sync m16n8k16 bf16 (exact in fp32),
//     epilogue adj = |S| * inv, write g_adj, deterministic partial row stats.
//     Block = 128x128 tile, 256 threads (8 warps: 4 in M, 2 in N).
// ---------------------------------------------------------------------------
__global__ void __launch_bounds__(256) k2_gemm(float inv) {
    __shared__ __nv_bfloat16 As[128][72];  // K-chunk 64 + pad 8
    __shared__ __nv_bfloat16 Bs[128][72];
    __shared__ float spsum[2][128];
    __shared__ float spsq [2][128];

    const int tid  = threadIdx.x;
    const int nt   = blockIdx.x, mt = blockIdx.y, b = blockIdx.z;
    const int m0   = mt * 128, n0 = nt * 128;
    const int wid  = tid >> 5, lane = tid & 31;
    const int wm   = wid & 3, wn = wid >> 2;       // warp tile 32(M) x 64(N)
    const int r    = lane >> 2;
    const int c2   = (lane & 3) * 2;

    const __nv_bfloat16* cbase = g_c + (size_t)b * NN * DD;

    float acc[2][8][4];
    #pragma unroll
    for (int mi = 0; mi < 2; ++mi)
        #pragma unroll
        for (int ni = 0; ni < 8; ++ni)
            #pragma unroll
            for (int u = 0; u < 4; ++u) acc[mi][ni][u] = 0.f;

    for (int kc = 0; kc < 4; ++kc) {
        const int k0g = kc * 64;
        #pragma unroll
        for (int l = 0; l < 4; ++l) {
            int id  = tid + l * 256;          // 0..1023
            int row = id >> 3, seg = id & 7;  // 8 x 16B per row
            uint4 va = *(const uint4*)(cbase + ((size_t)(m0 + row) * DD + k0g + seg * 8));
            *(uint4*)&As[row][seg * 8] = va;
            uint4 vb = *(const uint4*)(cbase + ((size_t)(n0 + row) * DD + k0g + seg * 8));
            *(uint4*)&Bs[row][seg * 8] = vb;
        }
        __syncthreads();

        #pragma unroll
        for (int ks = 0; ks < 4; ++ks) {
            const int k0 = ks * 16;
            unsigned a[2][4];
            #pragma unroll
            for (int mi = 0; mi < 2; ++mi) {
                int rb = wm * 32 + mi * 16;
                a[mi][0] = *(const unsigned*)&As[rb + r    ][k0 + c2    ];
                a[mi][1] = *(const unsigned*)&As[rb + r + 8][k0 + c2    ];
                a[mi][2] = *(const unsigned*)&As[rb + r    ][k0 + c2 + 8];
                a[mi][3] = *(const unsigned*)&As[rb + r + 8][k0 + c2 + 8];
            }
            #pragma unroll
            for (int ni = 0; ni < 8; ++ni) {
                int cb0 = wn * 64 + ni * 8;
                unsigned b0 = *(const unsigned*)&Bs[cb0 + r][k0 + c2    ];
                unsigned b1 = *(const unsigned*)&Bs[cb0 + r][k0 + c2 + 8];
                #pragma unroll
                for (int mi = 0; mi < 2; ++mi) {
                    asm volatile(
                        "mma.sync.aligned.m16n8k16.row.col.f32.bf16.bf16.f32 "
                        "{%0,%1,%2,%3},{%4,%5,%6,%7},{%8,%9},{%0,%1,%2,%3};\n"
                        : "+f"(acc[mi][ni][0]), "+f"(acc[mi][ni][1]),
                          "+f"(acc[mi][ni][2]), "+f"(acc[mi][ni][3])
                        : "r"(a[mi][0]), "r"(a[mi][1]), "r"(a[mi][2]), "r"(a[mi][3]),
                          "r"(b0), "r"(b1));
                }
            }
        }
        __syncthreads();
    }

    // epilogue: adj = |S|*inv, write, accumulate row partials deterministically
    float rsum[2][2] = {{0.f,0.f},{0.f,0.f}};
    float rsq [2][2] = {{0.f,0.f},{0.f,0.f}};
    #pragma unroll
    for (int mi = 0; mi < 2; ++mi) {
        int rg0 = m0 + wm * 32 + mi * 16 + r;
        #pragma unroll
        for (int ni = 0; ni < 8; ++ni) {
            int cg = n0 + wn * 64 + ni * 8 + c2;
            float a0 = fabsf(acc[mi][ni][0]) * inv;
            float a1 = fabsf(acc[mi][ni][1]) * inv;
            float a2 = fabsf(acc[mi][ni][2]) * inv;
            float a3 = fabsf(acc[mi][ni][3]) * inv;
            size_t base = ((size_t)(b * NN + rg0)) * NN + cg;
            *(float2*)&g_adj[base]            = make_float2(a0, a1);
            *(float2*)&g_adj[base + 8 * NN]   = make_float2(a2, a3);
            rsum[mi][0] += a0 + a1;      rsq[mi][0] += a0*a0 + a1*a1;
            rsum[mi][1] += a2 + a3;      rsq[mi][1] += a2*a2 + a3*a3;
        }
    }
    #pragma unroll
    for (int o = 1; o <= 2; o <<= 1) {
        #pragma unroll
        for (int mi = 0; mi < 2; ++mi)
            #pragma unroll
            for (int h = 0; h < 2; ++h) {
                rsum[mi][h] += __shfl_xor_sync(0xffffffffu, rsum[mi][h], o);
                rsq [mi][h] += __shfl_xor_sync(0xffffffffu, rsq [mi][h], o);
            }
    }
    if ((lane & 3) == 0) {
        #pragma unroll
        for (int mi = 0; mi < 2; ++mi)
            #pragma unroll
            for (int h = 0; h < 2; ++h) {
                int rl = wm * 32 + mi * 16 + h * 8 + r;
                spsum[wn][rl] = rsum[mi][h];
                spsq [wn][rl] = rsq [mi][h];
            }
    }
    __syncthreads();
    if (tid < 128) {
        float s = spsum[0][tid] + spsum[1][tid];
        float q = spsq [0][tid] + spsq [1][tid];
        int o = (b * 8 + nt) * NN + m0 + tid;
        g_psum[o] = s;
        g_psq [o] = q;
    }
}

// ---------------------------------------------------------------------------
// K3: finalize per-row mean / rstd over N=1024
// ---------------------------------------------------------------------------
__global__ void k3_stats() {
    int i = blockIdx.x * blockDim.x + threadIdx.x;   // 0..65535 = b*N+n
    int b = i >> 10, n = i & (NN - 1);
    float s = 0.f, q = 0.f;
    #pragma unroll
    for (int t = 0; t < 8; ++t) {
        int o = (b * 8 + t) * NN + n;
        s += g_psum[o];
        q += g_psq [o];
    }
    float mu  = s * (1.0f / NN);
    float var = q * (1.0f / NN) - mu * mu;
    g_mean[i] = mu;
    g_rstd[i] = rsqrtf(var + 1e-5f);
}

// ---------------------------------------------------------------------------
// K4: out = relu((adj - mu) * rstd * g[m] + b[m]) ; streaming float4 pass
// ---------------------------------------------------------------------------
__global__ void k4_final(const float* __restrict__ sg,
                         const float* __restrict__ sb,
                         float* __restrict__ out) {
    size_t idx = (size_t)blockIdx.x * blockDim.x + threadIdx.x; // float4 units
    int row = (int)(idx >> 8);        // b*N+n
    int m4  = (int)(idx & 255);
    float4 a  = ((const float4*)g_adj)[idx];
    float mu  = g_mean[row];
    float rs  = g_rstd[row];
    float4 g  = ((const float4*)sg)[m4];
    float4 bb = ((const float4*)sb)[m4];
    float4 o;
    o.x = fmaxf((a.x - mu) * rs * g.x + bb.x, 0.f);
    o.y = fmaxf((a.y - mu) * rs * g.y + bb.y, 0.f);
    o.z = fmaxf((a.z - mu) * rs * g.z + bb.z, 0.f);
    o.w = fmaxf((a.w - mu) * rs * g.w + bb.w, 0.f);
    ((float4*)out)[idx] = o;
}

// ---------------------------------------------------------------------------
extern "C" void kernel_launch(void* const* d_in, const int* in_sizes, int n_in,
                              void* d_out, int out_size) {
    const float* x        = (const float*)d_in[0];
    const float* conv_w   = (const float*)d_in[1];
    const float* conv_b   = (const float*)d_in[2];
    const float* time_g   = (const float*)d_in[3];
    const float* time_b   = (const float*)d_in[4];
    const float* static_g = (const float*)d_in[5];
    const float* static_b = (const float*)d_in[6];
    float* out = (float*)d_out;

    k1_emb_rank<<<dim3(NN / 8, BB), 256>>>(x, conv_w, conv_b, time_g, time_b);

    // norm is a constant: sum((k-127.5)^2, k=0..255) = D(D^2-1)/12 = 1398080
    float nv  = sqrtf(1398080.0f);
    float inv = 1.0f / (nv * nv + 1e-8f);
    k2_gemm<<<dim3(8, 8, BB), 256>>>(inv);

    k3_stats<<<(BB * NN) / 256, 256>>>();

    // 64*1024*1024/4 float4 elements = 16,777,216 -> 65536 blocks x 256
    k4_final<<<65536, 256>>>(static_g, static_b, out);
}

// round 7
// speedup vs baseline: 1.0687x; 1.0687x over previous
#include <cuda_runtime.h>
#include <cuda_bf16.h>
#include <math.h>
#include <stdint.h>

// ---------------------------------------------------------------------------
// Shapes: B=64, C=2, N=1024, T=13, D=256. Output [64,1024,1024] fp32.
// ---------------------------------------------------------------------------

#define BB   64
#define NN   1024
#define DD   256
#define CT   26      // C*T contraction length

// Scratch (device globals; allocation-free per harness rules)
__device__ __align__(16) __nv_bfloat16 g_c[BB * NN * DD];        // 32 MB  (rank-127.5 as bf16)
__device__ __align__(16) float g_adj[(size_t)BB * NN * NN];      // 268 MB
__device__ float g_psum[BB * 8 * NN];                            // per col-tile partial row sums
__device__ float g_psq [BB * 8 * NN];
__device__ float g_mean[BB * NN];
__device__ float g_rstd[BB * NN];

// upper-triangle tile list: 36 tiles of an 8x8 grid (mt <= nt)
__constant__ unsigned char c_mt[36] =
    {0,0,0,0,0,0,0,0, 1,1,1,1,1,1,1, 2,2,2,2,2,2, 3,3,3,3,3, 4,4,4,4, 5,5,5, 6,6, 7};
__constant__ unsigned char c_nt[36] =
    {0,1,2,3,4,5,6,7, 1,2,3,4,5,6,7, 2,3,4,5,6,7, 3,4,5,6,7, 4,5,6,7, 5,6,7, 6,7, 7};

__device__ __forceinline__ uint32_t smem_u32(const void* p) {
    uint32_t a;
    asm("{ .reg .u64 t; cvta.to.shared.u64 t, %1; cvt.u32.u64 %0, t; }"
        : "=r"(a) : "l"(p));
    return a;
}
__device__ __forceinline__ void ldsm_x4(uint32_t addr, uint32_t& r0, uint32_t& r1,
                                        uint32_t& r2, uint32_t& r3) {
    asm volatile("ldmatrix.sync.aligned.m8n8.x4.shared.b16 {%0,%1,%2,%3}, [%4];"
                 : "=r"(r0), "=r"(r1), "=r"(r2), "=r"(r3) : "r"(addr));
}
__device__ __forceinline__ void cp16(uint32_t dst, const void* src) {
    asm volatile("cp.async.cg.shared.global [%0], [%1], 16;" :: "r"(dst), "l"(src));
}

// ---------------------------------------------------------------------------
// K1: conv (einsum bcnt,dct->bnd) + bias + LayerNorm(D) + stable rank via
//     bitonic sort of (sortable_bits<<32 | idx). One block = 8 rows, 256 thr.
// ---------------------------------------------------------------------------
__global__ void k1_emb_rank(const float* __restrict__ x,
                            const float* __restrict__ conv_w,
                            const float* __restrict__ conv_b,
                            const float* __restrict__ time_g,
                            const float* __restrict__ time_b) {
    __shared__ float ws[DD * CT];          // 26.6 KB
    __shared__ float xs[8][CT];
    __shared__ unsigned long long keys[DD];
    __shared__ float red[16];

    const int tid = threadIdx.x;           // 0..255 == d
    const int b   = blockIdx.y;
    const int n0  = blockIdx.x * 8;

    for (int i = tid; i < DD * CT; i += 256) ws[i] = conv_w[i];
    if (tid < 8 * CT) {
        int r = tid / CT, j = tid % CT;
        int c = j / 13, t = j % 13;
        xs[r][j] = x[(((size_t)(b * 2 + c) * NN) + (n0 + r)) * 13 + t];
    }
    __syncthreads();

    const float tg = time_g[tid];
    const float tb = time_b[tid];
    const float cb = conv_b[tid];

    for (int r = 0; r < 8; ++r) {
        float acc = cb;
        #pragma unroll
        for (int j = 0; j < CT; ++j) acc += xs[r][j] * ws[tid * CT + j];

        float s = acc, q = acc * acc;
        #pragma unroll
        for (int o = 16; o; o >>= 1) {
            s += __shfl_xor_sync(0xffffffffu, s, o);
            q += __shfl_xor_sync(0xffffffffu, q, o);
        }
        if ((tid & 31) == 0) { red[tid >> 5] = s; red[8 + (tid >> 5)] = q; }
        __syncthreads();
        if (tid == 0) {
            float S = 0.f, Q = 0.f;
            #pragma unroll
            for (int i = 0; i < 8; ++i) { S += red[i]; Q += red[8 + i]; }
            float mu  = S * (1.0f / 256.0f);
            float var = Q * (1.0f / 256.0f) - mu * mu;
            red[0] = mu;
            red[1] = rsqrtf(var + 1e-5f);
        }
        __syncthreads();
        float v = (acc - red[0]) * red[1] * tg + tb;

        unsigned kb = __float_as_uint(v);
        kb = (kb & 0x80000000u) ? ~kb : (kb | 0x80000000u);
        keys[tid] = ((unsigned long long)kb << 32) | (unsigned)tid;
        __syncthreads();

        for (int k = 2; k <= 256; k <<= 1) {
            for (int j = k >> 1; j > 0; j >>= 1) {
                int p = tid ^ j;
                if (p > tid) {
                    bool up = ((tid & k) == 0);
                    unsigned long long a = keys[tid], bkey = keys[p];
                    if ((a > bkey) == up) { keys[tid] = bkey; keys[p] = a; }
                }
                __syncthreads();
            }
        }
        int idx = (int)(keys[tid] & 0xFFu);
        g_c[((size_t)(b * NN + n0 + r) << 8) + idx] =
            __float2bfloat16((float)tid - 127.5f);
        __syncthreads();
    }
}

// ---------------------------------------------------------------------------
// K2: symmetric bf16 GEMM, upper-triangle tiles only (36 of 64).
//     128x128 tile per CTA, K=256 in four 64-chunks, cp.async double buffer,
//     ldmatrix operand fetch, mma.sync m16n8k16 (exact in fp32).
//     Epilogue writes (mt,nt) block directly, (nt,mt) block via smem
//     transpose, plus deterministic row- and column-partial stats.
// ---------------------------------------------------------------------------
#define TILE_BYTES  18432          // 128 rows * 72 bf16 * 2B
#define STAGE_BYTES 36864          // A + B
#define DYN_SMEM    73728          // 2 stages

__global__ void __launch_bounds__(256, 2) k2_gemm(float inv) {
    extern __shared__ char dsm[];
    __shared__ float spsum[2][128], spsq[2][128];
    __shared__ float scsum[4][128], scsq[4][128];

    const uint32_t smb = smem_u32(dsm);
    const int tid  = threadIdx.x, lane = tid & 31, wid = tid >> 5;
    const int wm   = wid & 3, wn = wid >> 2;      // warp tile 32(M) x 64(N)
    const int ti   = blockIdx.x, b = blockIdx.y;
    const int mt   = c_mt[ti], nt = c_nt[ti];
    const int m0   = mt * 128, n0 = nt * 128;

    const __nv_bfloat16* cb = g_c + (size_t)b * NN * DD;

    // ldmatrix per-lane byte offsets (within a stage buffer)
    uint32_t aoff[2], boff[4];
    {
        const int l7  = lane & 7;
        const int g8  = (lane >> 3) & 1;
        const int g16 = lane >> 4;
        #pragma unroll
        for (int mi = 0; mi < 2; ++mi)
            aoff[mi] = (uint32_t)(((wm * 32 + mi * 16 + g8 * 8 + l7) * 72 + g16 * 8) * 2);
        #pragma unroll
        for (int p = 0; p < 4; ++p)
            boff[p] = (uint32_t)(TILE_BYTES +
                      ((wn * 64 + p * 16 + g16 * 8 + l7) * 72 + g8 * 8) * 2);
    }

    float acc[2][8][4];
    #pragma unroll
    for (int mi = 0; mi < 2; ++mi)
        #pragma unroll
        for (int ni = 0; ni < 8; ++ni)
            #pragma unroll
            for (int u = 0; u < 4; ++u) acc[mi][ni][u] = 0.f;

    // prologue: load K-chunk 0 into stage 0
    #pragma unroll
    for (int l = 0; l < 4; ++l) {
        int id = tid + l * 256;
        int row = id >> 3, seg = id & 7;
        uint32_t d = smb + row * 144 + seg * 16;
        cp16(d,              cb + (size_t)(m0 + row) * DD + seg * 8);
        cp16(d + TILE_BYTES, cb + (size_t)(n0 + row) * DD + seg * 8);
    }
    asm volatile("cp.async.commit_group;" ::: "memory");

    for (int kc = 0; kc < 4; ++kc) {
        if (kc < 3) {
            uint32_t sb = smb + (uint32_t)(((kc + 1) & 1) * STAGE_BYTES);
            const int kg = (kc + 1) * 64;
            #pragma unroll
            for (int l = 0; l < 4; ++l) {
                int id = tid + l * 256;
                int row = id >> 3, seg = id & 7;
                uint32_t d = sb + row * 144 + seg * 16;
                cp16(d,              cb + (size_t)(m0 + row) * DD + kg + seg * 8);
                cp16(d + TILE_BYTES, cb + (size_t)(n0 + row) * DD + kg + seg * 8);
            }
            asm volatile("cp.async.commit_group;" ::: "memory");
            asm volatile("cp.async.wait_group 1;" ::: "memory");
        } else {
            asm volatile("cp.async.wait_group 0;" ::: "memory");
        }
        __syncthreads();

        const uint32_t base = smb + (uint32_t)((kc & 1) * STAGE_BYTES);
        #pragma unroll
        for (int ks = 0; ks < 4; ++ks) {
            const uint32_t kb = base + ks * 32;   // 16 bf16 = 32 bytes per step
            uint32_t af[8], bf[16];
            ldsm_x4(kb + aoff[0], af[0], af[1], af[2], af[3]);
            ldsm_x4(kb + aoff[1], af[4], af[5], af[6], af[7]);
            #pragma unroll
            for (int p = 0; p < 4; ++p)
                ldsm_x4(kb + boff[p], bf[p*4], bf[p*4+1], bf[p*4+2], bf[p*4+3]);
            #pragma unroll
            for (int ni = 0; ni < 8; ++ni) {
                uint32_t b0 = bf[(ni >> 1) * 4 + (ni & 1) * 2];
                uint32_t b1 = bf[(ni >> 1) * 4 + (ni & 1) * 2 + 1];
                #pragma unroll
                for (int mi = 0; mi < 2; ++mi) {
                    asm volatile(
                        "mma.sync.aligned.m16n8k16.row.col.f32.bf16.bf16.f32 "
                        "{%0,%1,%2,%3},{%4,%5,%6,%7},{%8,%9},{%0,%1,%2,%3};\n"
                        : "+f"(acc[mi][ni][0]), "+f"(acc[mi][ni][1]),
                          "+f"(acc[mi][ni][2]), "+f"(acc[mi][ni][3])
                        : "r"(af[mi*4]), "r"(af[mi*4+1]),
                          "r"(af[mi*4+2]), "r"(af[mi*4+3]),
                          "r"(b0), "r"(b1));
                }
            }
        }
        __syncthreads();
    }

    // ---- epilogue ----
    const int r  = lane >> 2;
    const int c2 = (lane & 3) * 2;

    // scale in place: v = |corr| * inv
    #pragma unroll
    for (int mi = 0; mi < 2; ++mi)
        #pragma unroll
        for (int ni = 0; ni < 8; ++ni)
            #pragma unroll
            for (int u = 0; u < 4; ++u)
                acc[mi][ni][u] = fabsf(acc[mi][ni][u]) * inv;

    // direct (mt,nt) block writes + per-thread row partials
    float rsum[2][2] = {{0.f,0.f},{0.f,0.f}};
    float rsq [2][2] = {{0.f,0.f},{0.f,0.f}};
    #pragma unroll
    for (int mi = 0; mi < 2; ++mi) {
        int rg0 = m0 + wm * 32 + mi * 16 + r;
        #pragma unroll
        for (int ni = 0; ni < 8; ++ni) {
            int cg = n0 + wn * 64 + ni * 8 + c2;
            float a0 = acc[mi][ni][0], a1 = acc[mi][ni][1];
            float a2 = acc[mi][ni][2], a3 = acc[mi][ni][3];
            size_t basei = (size_t)(b * NN + rg0) * NN + cg;
            *(float2*)&g_adj[basei]          = make_float2(a0, a1);
            *(float2*)&g_adj[basei + 8 * NN] = make_float2(a2, a3);
            rsum[mi][0] += a0 + a1;   rsq[mi][0] += a0*a0 + a1*a1;
            rsum[mi][1] += a2 + a3;   rsq[mi][1] += a2*a2 + a3*a3;
        }
    }
    #pragma unroll
    for (int o = 1; o <= 2; o <<= 1) {
        #pragma unroll
        for (int mi = 0; mi < 2; ++mi)
            #pragma unroll
            for (int h = 0; h < 2; ++h) {
                rsum[mi][h] += __shfl_xor_sync(0xffffffffu, rsum[mi][h], o);
                rsq [mi][h] += __shfl_xor_sync(0xffffffffu, rsq [mi][h], o);
            }
    }
    if ((lane & 3) == 0) {
        #pragma unroll
        for (int mi = 0; mi < 2; ++mi)
            #pragma unroll
            for (int h = 0; h < 2; ++h) {
                int rl = wm * 32 + mi * 16 + h * 8 + r;
                spsum[wn][rl] = rsum[mi][h];
                spsq [wn][rl] = rsq [mi][h];
            }
    }

    if (mt != nt) {
        // column partials (become row partials of the transposed block)
        #pragma unroll
        for (int ni = 0; ni < 8; ++ni) {
            float v00 = acc[0][ni][0], v02 = acc[0][ni][2];
            float v10 = acc[1][ni][0], v12 = acc[1][ni][2];
            float v01 = acc[0][ni][1], v03 = acc[0][ni][3];
            float v11 = acc[1][ni][1], v13 = acc[1][ni][3];
            float cs0 = v00 + v02 + v10 + v12;
            float cs1 = v01 + v03 + v11 + v13;
            float cq0 = v00*v00 + v02*v02 + v10*v10 + v12*v12;
            float cq1 = v01*v01 + v03*v03 + v11*v11 + v13*v13;
            #pragma unroll
            for (int o = 4; o <= 16; o <<= 1) {
                cs0 += __shfl_xor_sync(0xffffffffu, cs0, o);
                cs1 += __shfl_xor_sync(0xffffffffu, cs1, o);
                cq0 += __shfl_xor_sync(0xffffffffu, cq0, o);
                cq1 += __shfl_xor_sync(0xffffffffu, cq1, o);
            }
            if (lane < 4) {
                int c = wn * 64 + ni * 8 + lane * 2;
                scsum[wm][c]     = cs0;  scsum[wm][c + 1] = cs1;
                scsq [wm][c]     = cq0;  scsq [wm][c + 1] = cq1;
            }
        }

        // transposed (nt,mt) block: stage 32x64 per warp, write coalesced
        float* stg = (float*)(dsm + wid * 8320);   // 32 x 65 fp32
        #pragma unroll
        for (int mi = 0; mi < 2; ++mi) {
            int ml = mi * 16 + r;
            #pragma unroll
            for (int ni = 0; ni < 8; ++ni) {
                int cl = ni * 8 + c2;
                stg[ml * 65 + cl]           = acc[mi][ni][0];
                stg[ml * 65 + cl + 1]       = acc[mi][ni][1];
                stg[(ml + 8) * 65 + cl]     = acc[mi][ni][2];
                stg[(ml + 8) * 65 + cl + 1] = acc[mi][ni][3];
            }
        }
        __syncwarp();
        #pragma unroll 8
        for (int cc = 0; cc < 64; ++cc) {
            g_adj[(size_t)(b * NN + n0 + wn * 64 + cc) * NN + m0 + wm * 32 + lane] =
                stg[lane * 65 + cc];
        }
    }

    __syncthreads();
    if (tid < 128) {
        float s = spsum[0][tid] + spsum[1][tid];
        float q = spsq [0][tid] + spsq [1][tid];
        g_psum[(b * 8 + nt) * NN + m0 + tid] = s;
        g_psq [(b * 8 + nt) * NN + m0 + tid] = q;
        if (mt != nt) {
            float cs = scsum[0][tid] + scsum[1][tid] + scsum[2][tid] + scsum[3][tid];
            float cq = scsq [0][tid] + scsq [1][tid] + scsq [2][tid] + scsq [3][tid];
            g_psum[(b * 8 + mt) * NN + n0 + tid] = cs;
            g_psq [(b * 8 + mt) * NN + n0 + tid] = cq;
        }
    }
}

// ---------------------------------------------------------------------------
// K3: finalize per-row mean / rstd over N=1024
// ---------------------------------------------------------------------------
__global__ void k3_stats() {
    int i = blockIdx.x * blockDim.x + threadIdx.x;   // 0..65535 = b*N+n
    int b = i >> 10, n = i & (NN - 1);
    float s = 0.f, q = 0.f;
    #pragma unroll
    for (int t = 0; t < 8; ++t) {
        int o = (b * 8 + t) * NN + n;
        s += g_psum[o];
        q += g_psq [o];
    }
    float mu  = s * (1.0f / NN);
    float var = q * (1.0f / NN) - mu * mu;
    g_mean[i] = mu;
    g_rstd[i] = rsqrtf(var + 1e-5f);
}

// ---------------------------------------------------------------------------
// K4: out = relu((adj - mu) * rstd * g[m] + b[m]) ; streaming float4 pass
// ---------------------------------------------------------------------------
__global__ void k4_final(const float* __restrict__ sg,
                         const float* __restrict__ sb,
                         float* __restrict__ out) {
    size_t idx = (size_t)blockIdx.x * blockDim.x + threadIdx.x; // float4 units
    int row = (int)(idx >> 8);        // b*N+n
    int m4  = (int)(idx & 255);
    float4 a  = ((const float4*)g_adj)[idx];
    float mu  = g_mean[row];
    float rs  = g_rstd[row];
    float4 g  = ((const float4*)sg)[m4];
    float4 bb = ((const float4*)sb)[m4];
    float4 o;
    o.x = fmaxf((a.x - mu) * rs * g.x + bb.x, 0.f);
    o.y = fmaxf((a.y - mu) * rs * g.y + bb.y, 0.f);
    o.z = fmaxf((a.z - mu) * rs * g.z + bb.z, 0.f);
    o.w = fmaxf((a.w - mu) * rs * g.w + bb.w, 0.f);
    ((float4*)out)[idx] = o;
}

// ---------------------------------------------------------------------------
extern "C" void kernel_launch(void* const* d_in, const int* in_sizes, int n_in,
                              void* d_out, int out_size) {
    const float* x        = (const float*)d_in[0];
    const float* conv_w   = (const float*)d_in[1];
    const float* conv_b   = (const float*)d_in[2];
    const float* time_g   = (const float*)d_in[3];
    const float* time_b   = (const float*)d_in[4];
    const float* static_g = (const float*)d_in[5];
    const float* static_b = (const float*)d_in[6];
    float* out = (float*)d_out;

    static int configured = 0;
    if (!configured) {
        cudaFuncSetAttribute(k2_gemm,
                             cudaFuncAttributeMaxDynamicSharedMemorySize, DYN_SMEM);
        configured = 1;
    }

    k1_emb_rank<<<dim3(NN / 8, BB), 256>>>(x, conv_w, conv_b, time_g, time_b);

    // norm is a constant: sum((k-127.5)^2, k=0..255) = D(D^2-1)/12 = 1398080
    float nv  = sqrtf(1398080.0f);
    float inv = 1.0f / (nv * nv + 1e-8f);
    k2_gemm<<<dim3(36, BB), 256, DYN_SMEM>>>(inv);

    k3_stats<<<(BB * NN) / 256, 256>>>();

    k4_final<<<65536, 256>>>(static_g, static_b, out);
}